// round 1
// baseline (speedup 1.0000x reference)
#include <cuda_runtime.h>

// Problem constants (fixed shapes from reference setup_inputs)
#define BB      16
#define NPTS    1024          // H*W
#define DD      128
#define KK      32
#define GPB     8             // groups (blocks) per batch
#define PPB     (NPTS / GPB)  // 128 points per block
#define TILE    32
#define NTILES  (PPB / TILE)  // 4
#define NTHREADS 256

__global__ void ev_zero_kernel(float* __restrict__ out) {
    int i = blockIdx.x * blockDim.x + threadIdx.x;
    ((float4*)out)[i] = make_float4(0.f, 0.f, 0.f, 0.f);
}

__global__ __launch_bounds__(NTHREADS, 1)
void ev_encode_kernel(const float* __restrict__ x,
                      const float* __restrict__ cw,
                      const float* __restrict__ scale,
                      float* __restrict__ out) {
    // Swizzled codewords: row k stored as 32 float4 chunks, logical chunk d4 at
    // physical slot (d4 ^ k). Per-lane row reads then touch 32 distinct chunks
    // -> conflict-free (4-wavefront minimum for 512B).
    __shared__ float c_sw[KK * DD];        // 16 KB
    __shared__ float x_sh[TILE * DD];      // 16 KB
    __shared__ float A_sh[TILE * KK];      // 4 KB
    __shared__ float sk[KK], m2sk[KK], skc2[KK];

    const int t    = threadIdx.x;
    const int lane = t & 31;
    const int w    = t >> 5;               // 0..7
    const int b    = blockIdx.x / GPB;
    const int g    = blockIdx.x % GPB;

    // ---- load codewords into swizzled SMEM ----
    for (int idx = t; idx < KK * DD; idx += NTHREADS) {
        int k  = idx >> 7;                 // / 128
        int d  = idx & 127;
        int d4 = d >> 2, j = d & 3;
        c_sw[k * DD + (((d4 ^ k) & 31) << 2) + j] = cw[idx];
    }
    __syncthreads();

    // ---- per-k constants: sk = scale_k, m2sk = -2*scale_k, skc2 = scale_k*||c_k||^2 ----
    if (t < KK) {
        float c2 = 0.f;
        const float4* row = (const float4*)c_sw + t * 32;
        #pragma unroll
        for (int d4 = 0; d4 < 32; ++d4) {
            float4 c = row[d4 ^ t];
            c2 += c.x * c.x + c.y * c.y + c.z * c.z + c.w * c.w;
        }
        float s = scale[t];
        sk[t] = s; m2sk[t] = -2.f * s; skc2[t] = s * c2;
    }
    // visibility of sk/... is guaranteed by the __syncthreads inside the tile loop

    // Stage-2 ownership: thread (tk = lane, td = w) owns k = tk, d in [td*16, td*16+16)
    const int tk = lane;
    const int td = w;
    float4 acc[4] = {};
    float  sA = 0.f;

    const float* xb = x + ((size_t)b * NPTS + (size_t)g * PPB) * DD;

    for (int tile = 0; tile < NTILES; ++tile) {
        // ---- load x tile (32 pts x 128 floats), coalesced float4 ----
        const float4* xg  = (const float4*)(xb + tile * TILE * DD);
        float4*       xs4 = (float4*)x_sh;
        #pragma unroll
        for (int i = t; i < TILE * DD / 4; i += NTHREADS) xs4[i] = xg[i];
        __syncthreads();   // also covers sk/m2sk/skc2 on first iteration

        // ---- Stage 1: warp w handles points p0..p0+3; lane = codeword k ----
        {
            const int p0 = w * 4;

            // x2 per point: lane-partial over 4 strided dims + warp reduce
            float x2p[4];
            #pragma unroll
            for (int p = 0; p < 4; ++p) {
                float s = 0.f;
                #pragma unroll
                for (int j = 0; j < 4; ++j) {
                    float v = x_sh[(p0 + p) * DD + lane + 32 * j];
                    s = fmaf(v, v, s);
                }
                #pragma unroll
                for (int o = 16; o; o >>= 1) s += __shfl_xor_sync(0xffffffffu, s, o);
                x2p[p] = s;
            }

            // xc_k for 4 points: 1 codeword float4 amortized over 4 points
            float xc[4] = {0.f, 0.f, 0.f, 0.f};
            const float4* crow = (const float4*)c_sw + lane * 32;
            const float4* xr   = (const float4*)x_sh;
            #pragma unroll
            for (int d4 = 0; d4 < 32; ++d4) {
                float4 c = crow[d4 ^ lane];
                #pragma unroll
                for (int p = 0; p < 4; ++p) {
                    float4 xv = xr[(p0 + p) * 32 + d4];
                    float acc0 = fmaf(c.x, xv.x, fmaf(c.y, xv.y, fmaf(c.z, xv.z, c.w * xv.w)));
                    xc[p] += acc0;
                }
            }

            // scaled logits + warp softmax over K=32
            float skl = sk[lane], m2 = m2sk[lane], sc2 = skc2[lane];
            #pragma unroll
            for (int p = 0; p < 4; ++p) {
                float SL = fmaf(skl, x2p[p], fmaf(m2, xc[p], sc2));
                float m = SL;
                #pragma unroll
                for (int o = 16; o; o >>= 1) m = fmaxf(m, __shfl_xor_sync(0xffffffffu, m, o));
                float e = __expf(SL - m);
                float ssum = e;
                #pragma unroll
                for (int o = 16; o; o >>= 1) ssum += __shfl_xor_sync(0xffffffffu, ssum, o);
                A_sh[(p0 + p) * KK + lane] = e * (1.f / ssum);
            }
        }
        __syncthreads();

        // ---- Stage 2: E[k][d] += A[n][k] * x[n][d], register-resident ----
        {
            const float4* xr = (const float4*)x_sh;
            #pragma unroll 8
            for (int p = 0; p < TILE; ++p) {
                float a = A_sh[p * KK + tk];       // consecutive across warp
                sA += a;
                #pragma unroll
                for (int q = 0; q < 4; ++q) {
                    float4 xv = xr[p * 32 + td * 4 + q];  // uniform across warp -> broadcast
                    acc[q].x = fmaf(a, xv.x, acc[q].x);
                    acc[q].y = fmaf(a, xv.y, acc[q].y);
                    acc[q].z = fmaf(a, xv.z, acc[q].z);
                    acc[q].w = fmaf(a, xv.w, acc[q].w);
                }
            }
        }
        __syncthreads();   // protect x_sh/A_sh before next tile's load
    }

    // ---- epilogue: E[b][tk][d] += acc - sA * c[tk][d]  (8 partials per element) ----
    float* ob = out + ((size_t)b * KK + tk) * DD;
    const float4* crow = (const float4*)c_sw + tk * 32;
    #pragma unroll
    for (int q = 0; q < 4; ++q) {
        int d4 = td * 4 + q;
        float4 c = crow[d4 ^ tk];
        atomicAdd(&ob[d4 * 4 + 0], fmaf(-sA, c.x, acc[q].x));
        atomicAdd(&ob[d4 * 4 + 1], fmaf(-sA, c.y, acc[q].y));
        atomicAdd(&ob[d4 * 4 + 2], fmaf(-sA, c.z, acc[q].z));
        atomicAdd(&ob[d4 * 4 + 3], fmaf(-sA, c.w, acc[q].w));
    }
}

extern "C" void kernel_launch(void* const* d_in, const int* in_sizes, int n_in,
                              void* d_out, int out_size) {
    const float* x  = (const float*)d_in[0];   // [16,32,32,128]
    const float* cw = (const float*)d_in[1];   // [32,128]
    const float* sc = (const float*)d_in[2];   // [32]
    float* out = (float*)d_out;                // [16,32,128] = 65536 floats

    // out is poisoned; atomics need zeros
    ev_zero_kernel<<<(BB * KK * DD / 4) / 256, 256>>>(out);
    ev_encode_kernel<<<BB * GPB, NTHREADS>>>(x, cw, sc, out);
}

// round 2
// speedup vs baseline: 1.1359x; 1.1359x over previous
#include <cuda_runtime.h>

// Shapes fixed by reference setup_inputs()
#define BB      16
#define NPTS    1024          // H*W
#define DD      128           // = 32 float4 chunks
#define KK      32
#define GPB     16            // groups (CTAs) per batch
#define PPB     (NPTS / GPB)  // 64 points per CTA
#define NTHREADS 256

// Shared layout (dynamic): xs[64][34] float4 | cs[32][34] float4 | As[64*33] float
#define XS_STRIDE 34
#define CS_STRIDE 34
#define AS_STRIDE 33
#define XS_BYTES  (PPB * XS_STRIDE * 16)            // 34816
#define CS_BYTES  (KK * CS_STRIDE * 16)             // 17408
#define AS_BYTES  (PPB * AS_STRIDE * 4)             // 8448
#define SMEM_BYTES (XS_BYTES + CS_BYTES + AS_BYTES) // 60672

__device__ __forceinline__ unsigned long long ffma2_(unsigned long long a,
                                                     unsigned long long b,
                                                     unsigned long long c) {
    unsigned long long d;
    asm("fma.rn.f32x2 %0, %1, %2, %3;" : "=l"(d) : "l"(a), "l"(b), "l"(c));
    return d;
}
__device__ __forceinline__ unsigned long long pack2(float lo, float hi) {
    unsigned long long r;
    asm("mov.b64 %0, {%1, %2};" : "=l"(r) : "f"(lo), "f"(hi));
    return r;
}
__device__ __forceinline__ float2 unpack2(unsigned long long v) {
    float2 r;
    asm("mov.b64 {%0, %1}, %2;" : "=f"(r.x), "=f"(r.y) : "l"(v));
    return r;
}

__global__ void ev_zero_kernel(float* __restrict__ out) {
    int i = blockIdx.x * blockDim.x + threadIdx.x;
    ((float4*)out)[i] = make_float4(0.f, 0.f, 0.f, 0.f);
}

__global__ __launch_bounds__(NTHREADS, 2)
void ev_encode_kernel(const float* __restrict__ x,
                      const float* __restrict__ cw,
                      const float* __restrict__ scale,
                      float* __restrict__ out) {
    extern __shared__ char sraw[];
    float4* xs = (float4*)sraw;                          // [PPB][34]
    float4* cs = (float4*)(sraw + XS_BYTES);             // [KK][34]
    float*  As = (float*)(sraw + XS_BYTES + CS_BYTES);   // [PPB][33]

    const int t    = threadIdx.x;
    const int lane = t & 31;
    const int w    = t >> 5;              // 0..7
    const int b    = blockIdx.x >> 4;
    const int g    = blockIdx.x & 15;
    const int mi   = lane & 1;            // point-group within warp (2 x 4 pts)
    const int ni   = lane >> 1;           // k-pair index (16 pairs = 32 k)

    // ---- Phase A1: load x tile (64 pts x 32 float4), rotated slot = (d4+pt)&31 ----
    const float4* xg = (const float4*)(x + ((size_t)b * NPTS + (size_t)g * PPB) * DD);
    #pragma unroll
    for (int i = 0; i < 8; ++i) {
        int idx = t + i * NTHREADS;       // 0..2047
        int p  = idx >> 5;
        int d4 = idx & 31;
        xs[p * XS_STRIDE + ((d4 + p) & 31)] = xg[idx];
    }

    // ---- Phase A2: build augmented codewords: w_k = -2*s_k*c_k, slot=(d4 + k/2)&31;
    //      slot 32 = (s_k, s_k*||c_k||^2, 0, 0). Warp w builds rows 4w..4w+3. ----
    #pragma unroll
    for (int j = 0; j < 4; ++j) {
        int k = w * 4 + j;
        float4 c = ((const float4*)cw)[k * 32 + lane];
        float s  = scale[k];
        float c2 = c.x * c.x + c.y * c.y + c.z * c.z + c.w * c.w;
        #pragma unroll
        for (int o = 16; o; o >>= 1) c2 += __shfl_xor_sync(0xffffffffu, c2, o);
        float m2 = -2.f * s;
        cs[k * CS_STRIDE + ((lane + (k >> 1)) & 31)] =
            make_float4(m2 * c.x, m2 * c.y, m2 * c.z, m2 * c.w);
        if (lane == 0)
            cs[k * CS_STRIDE + 32] = make_float4(s, s * c2, 0.f, 0.f);
    }
    __syncthreads();

    // ---- Phase B: per-point ||x||^2 for this warp's 8 points (kept in regs) ----
    float x2p[8];
    #pragma unroll
    for (int j = 0; j < 8; ++j) {
        int p = w * 8 + j;
        float4 v = xs[p * XS_STRIDE + ((lane + p) & 31)];
        float s2 = v.x * v.x + v.y * v.y + v.z * v.z + v.w * v.w;
        #pragma unroll
        for (int o = 16; o; o >>= 1) s2 += __shfl_xor_sync(0xffffffffu, s2, o);
        x2p[j] = s2;
    }

    // ---- Phase C: stage-1 GEMM (logits), register-tiled 4 pts x 2 k per lane ----
    unsigned long long acc[4][2][2];
    #pragma unroll
    for (int p = 0; p < 4; ++p)
        #pragma unroll
        for (int r = 0; r < 2; ++r) { acc[p][r][0] = 0ull; acc[p][r][1] = 0ull; }

    const int pbase = w * 8 + mi * 4;
    const ulonglong2* cs2 = (const ulonglong2*)cs;
    const ulonglong2* xs2 = (const ulonglong2*)xs;

    #pragma unroll 4
    for (int d4 = 0; d4 < 32; ++d4) {
        int cslot = (d4 + ni) & 31;
        ulonglong2 cv0 = cs2[(2 * ni + 0) * CS_STRIDE + cslot];
        ulonglong2 cv1 = cs2[(2 * ni + 1) * CS_STRIDE + cslot];
        #pragma unroll
        for (int p = 0; p < 4; ++p) {
            int pt = pbase + p;
            ulonglong2 xv = xs2[pt * XS_STRIDE + ((d4 + pt) & 31)];
            acc[p][0][0] = ffma2_(cv0.x, xv.x, acc[p][0][0]);
            acc[p][0][1] = ffma2_(cv0.y, xv.y, acc[p][0][1]);
            acc[p][1][0] = ffma2_(cv1.x, xv.x, acc[p][1][0]);
            acc[p][1][1] = ffma2_(cv1.y, xv.y, acc[p][1][1]);
        }
    }

    // chunk-32 tail constants for this lane's 2 k values
    float4 cc0 = cs[(2 * ni + 0) * CS_STRIDE + 32];   // (s, s*c2, 0, 0)
    float4 cc1 = cs[(2 * ni + 1) * CS_STRIDE + 32];

    // ---- softmax over K=32 (butterfly over ni bits; mi bit untouched) ----
    #pragma unroll
    for (int p = 0; p < 4; ++p) {
        float x2 = x2p[mi * 4 + p];
        float2 a0 = unpack2(acc[p][0][0]), b0 = unpack2(acc[p][0][1]);
        float2 a1 = unpack2(acc[p][1][0]), b1 = unpack2(acc[p][1][1]);
        float SL0 = (a0.x + a0.y) + (b0.x + b0.y) + fmaf(cc0.x, x2, cc0.y);
        float SL1 = (a1.x + a1.y) + (b1.x + b1.y) + fmaf(cc1.x, x2, cc1.y);
        float m = fmaxf(SL0, SL1);
        #pragma unroll
        for (int o = 2; o <= 16; o <<= 1) m = fmaxf(m, __shfl_xor_sync(0xffffffffu, m, o));
        float e0 = __expf(SL0 - m);
        float e1 = __expf(SL1 - m);
        float ssum = e0 + e1;
        #pragma unroll
        for (int o = 2; o <= 16; o <<= 1) ssum += __shfl_xor_sync(0xffffffffu, ssum, o);
        float inv = 1.f / ssum;
        int pt = pbase + p;
        As[pt * AS_STRIDE + 2 * ni + 0] = e0 * inv;
        As[pt * AS_STRIDE + 2 * ni + 1] = e1 * inv;
    }
    __syncthreads();

    // ---- Phase D: stage-2  E[k][d] = sum_p A[p][k]*x[p][d]; lane=k, warp owns 16 d ----
    unsigned long long acc2[8];
    #pragma unroll
    for (int q = 0; q < 8; ++q) acc2[q] = 0ull;
    float sA = 0.f;
    const int d4b = w * 4;

    #pragma unroll 4
    for (int p = 0; p < PPB; ++p) {
        float a = As[p * AS_STRIDE + lane];
        sA += a;
        unsigned long long a2 = pack2(a, a);
        #pragma unroll
        for (int q = 0; q < 4; ++q) {
            ulonglong2 xv = xs2[p * XS_STRIDE + ((d4b + q + p) & 31)]; // broadcast
            acc2[2 * q + 0] = ffma2_(a2, xv.x, acc2[2 * q + 0]);
            acc2[2 * q + 1] = ffma2_(a2, xv.y, acc2[2 * q + 1]);
        }
    }

    // ---- epilogue: out[b][k][d] += acc2 - sA * c[k][d] ----
    const float4* crow = (const float4*)(cw + (size_t)lane * DD);
    float* ob = out + ((size_t)b * KK + lane) * DD;
    #pragma unroll
    for (int q = 0; q < 4; ++q) {
        int d4 = d4b + q;
        float4 c = crow[d4];
        float2 lo = unpack2(acc2[2 * q + 0]);
        float2 hi = unpack2(acc2[2 * q + 1]);
        atomicAdd(&ob[4 * d4 + 0], fmaf(-sA, c.x, lo.x));
        atomicAdd(&ob[4 * d4 + 1], fmaf(-sA, c.y, lo.y));
        atomicAdd(&ob[4 * d4 + 2], fmaf(-sA, c.z, hi.x));
        atomicAdd(&ob[4 * d4 + 3], fmaf(-sA, c.w, hi.y));
    }
}

extern "C" void kernel_launch(void* const* d_in, const int* in_sizes, int n_in,
                              void* d_out, int out_size) {
    const float* x  = (const float*)d_in[0];   // [16,32,32,128]
    const float* cw = (const float*)d_in[1];   // [32,128]
    const float* sc = (const float*)d_in[2];   // [32]
    float* out = (float*)d_out;                // [16,32,128]

    cudaFuncSetAttribute(ev_encode_kernel,
                         cudaFuncAttributeMaxDynamicSharedMemorySize, SMEM_BYTES);

    ev_zero_kernel<<<(BB * KK * DD / 4) / 256, 256>>>(out);
    ev_encode_kernel<<<BB * GPB, NTHREADS, SMEM_BYTES>>>(x, cw, sc, out);
}

// round 3
// speedup vs baseline: 1.5389x; 1.3547x over previous
#include <cuda_runtime.h>

// Shapes fixed by reference setup_inputs()
#define BB      16
#define NPTS    1024          // H*W
#define DD      128           // = 32 float4 chunks
#define KK      32
#define GPB     16            // chunks (CTAs) per batch
#define PPB     (NPTS / GPB)  // 64 points per CTA
#define NTHREADS 256
#define NCHUNK  (BB * GPB)    // 256

// Shared layout: xs[64][33] f4 | cs[32][34] f4 | As[64][33] f | x2s[64] f
#define XS_STRIDE 33
#define CS_STRIDE 34
#define AS_STRIDE 33
#define XS_BYTES  (PPB * XS_STRIDE * 16)            // 33792
#define CS_BYTES  (KK * CS_STRIDE * 16)             // 17408
#define AS_BYTES  (PPB * AS_STRIDE * 4)             // 8448
#define SMEM_BYTES (XS_BYTES + CS_BYTES + AS_BYTES + PPB * 4)  // 59904

// Cross-CTA partial tiles: [chunk][d][k] (transposed for coalesced STG/LDG)
__device__ float g_Ep[NCHUNK * KK * DD];            // 4 MB scratch

__device__ __forceinline__ unsigned long long ffma2_(unsigned long long a,
                                                     unsigned long long b,
                                                     unsigned long long c) {
    unsigned long long d;
    asm("fma.rn.f32x2 %0, %1, %2, %3;" : "=l"(d) : "l"(a), "l"(b), "l"(c));
    return d;
}
__device__ __forceinline__ unsigned long long pack2(float lo, float hi) {
    unsigned long long r;
    asm("mov.b64 %0, {%1, %2};" : "=l"(r) : "f"(lo), "f"(hi));
    return r;
}
__device__ __forceinline__ float2 unpack2(unsigned long long v) {
    float2 r;
    asm("mov.b64 {%0, %1}, %2;" : "=f"(r.x), "=f"(r.y) : "l"(v));
    return r;
}

__global__ __launch_bounds__(NTHREADS, 2)
void ev_encode_kernel(const float* __restrict__ x,
                      const float* __restrict__ cw,
                      const float* __restrict__ scale) {
    extern __shared__ char sraw[];
    float4* xs  = (float4*)sraw;                          // [PPB][33]
    float4* cs  = (float4*)(sraw + XS_BYTES);             // [KK][34] rotated
    float*  As  = (float*)(sraw + XS_BYTES + CS_BYTES);   // [PPB][33]
    float*  x2s = As + PPB * AS_STRIDE;                   // [PPB]

    const int t    = threadIdx.x;
    const int lane = t & 31;
    const int w    = t >> 5;              // 0..7
    const int b    = blockIdx.x >> 4;
    const int g    = blockIdx.x & 15;
    const int mi   = lane & 1;            // point-subgroup (2 x 4 pts)
    const int ni   = lane >> 1;           // k-pair index (16 pairs)

    // ---- Phase A1: stage x tile; warp w loads complete rows w, w+8, ...
    //      chunk = lane -> fold ||x||^2 reduction into the staging pass ----
    const float4* xg = (const float4*)(x + ((size_t)b * NPTS + (size_t)g * PPB) * DD);
    #pragma unroll
    for (int i = 0; i < 8; ++i) {
        int p = w + 8 * i;
        float4 v = xg[p * 32 + lane];
        xs[p * XS_STRIDE + lane] = v;
        float s2 = v.x * v.x + v.y * v.y + v.z * v.z + v.w * v.w;
        #pragma unroll
        for (int o = 16; o; o >>= 1) s2 += __shfl_xor_sync(0xffffffffu, s2, o);
        if (lane == 0) x2s[p] = s2;
    }

    // ---- Phase A2: augmented codewords w_k = -2*s_k*c_k at slot (d4 + k/2)&31;
    //      slot 32 = (s_k, s_k*||c_k||^2, 0, 0). Warp w builds rows 4w..4w+3. ----
    #pragma unroll
    for (int j = 0; j < 4; ++j) {
        int k = w * 4 + j;
        float4 c = ((const float4*)cw)[k * 32 + lane];
        float s  = scale[k];
        float c2 = c.x * c.x + c.y * c.y + c.z * c.z + c.w * c.w;
        #pragma unroll
        for (int o = 16; o; o >>= 1) c2 += __shfl_xor_sync(0xffffffffu, c2, o);
        float m2 = -2.f * s;
        cs[k * CS_STRIDE + ((lane + (k >> 1)) & 31)] =
            make_float4(m2 * c.x, m2 * c.y, m2 * c.z, m2 * c.w);
        if (lane == 0)
            cs[k * CS_STRIDE + 32] = make_float4(s, s * c2, 0.f, 0.f);
    }
    __syncthreads();

    // ---- Phase C: stage-1 GEMM (logits), 4 pts x 2 k per lane, folded accs ----
    unsigned long long acc[4][2];
    #pragma unroll
    for (int p = 0; p < 4; ++p) { acc[p][0] = 0ull; acc[p][1] = 0ull; }

    const int pbase = w * 8 + mi * 4;
    const ulonglong2* xs2 = (const ulonglong2*)xs;
    const ulonglong2* csrow0 = (const ulonglong2*)cs + (2 * ni + 0) * CS_STRIDE;
    const ulonglong2* csrow1 = (const ulonglong2*)cs + (2 * ni + 1) * CS_STRIDE;

    #pragma unroll 8
    for (int d4 = 0; d4 < 32; ++d4) {
        int cslot = (d4 + ni) & 31;
        ulonglong2 cv0 = csrow0[cslot];
        ulonglong2 cv1 = csrow1[cslot];
        #pragma unroll
        for (int p = 0; p < 4; ++p) {
            ulonglong2 xv = xs2[(pbase + p) * XS_STRIDE + d4];   // linear in d4
            acc[p][0] = ffma2_(cv0.x, xv.x, acc[p][0]);
            acc[p][0] = ffma2_(cv0.y, xv.y, acc[p][0]);
            acc[p][1] = ffma2_(cv1.x, xv.x, acc[p][1]);
            acc[p][1] = ffma2_(cv1.y, xv.y, acc[p][1]);
        }
    }

    float4 cc0 = cs[(2 * ni + 0) * CS_STRIDE + 32];   // (s, s*c2, 0, 0)
    float4 cc1 = cs[(2 * ni + 1) * CS_STRIDE + 32];

    // ---- softmax over K=32 (butterfly on ni bits; mi bit untouched) ----
    #pragma unroll
    for (int p = 0; p < 4; ++p) {
        float x2 = x2s[pbase + p];                     // broadcast LDS
        float2 u0 = unpack2(acc[p][0]);
        float2 u1 = unpack2(acc[p][1]);
        float SL0 = (u0.x + u0.y) + fmaf(cc0.x, x2, cc0.y);
        float SL1 = (u1.x + u1.y) + fmaf(cc1.x, x2, cc1.y);
        float m = fmaxf(SL0, SL1);
        #pragma unroll
        for (int o = 2; o <= 16; o <<= 1) m = fmaxf(m, __shfl_xor_sync(0xffffffffu, m, o));
        float e0 = __expf(SL0 - m);
        float e1 = __expf(SL1 - m);
        float ssum = e0 + e1;
        #pragma unroll
        for (int o = 2; o <= 16; o <<= 1) ssum += __shfl_xor_sync(0xffffffffu, ssum, o);
        float inv = 1.f / ssum;
        As[(pbase + p) * AS_STRIDE + 2 * ni + 0] = e0 * inv;
        As[(pbase + p) * AS_STRIDE + 2 * ni + 1] = e1 * inv;
    }
    __syncthreads();

    // ---- Phase D: E[k][d] = sum_p A[p][k]*x[p][d]; lane=k, warp owns 16 d ----
    unsigned long long acc2[8];
    #pragma unroll
    for (int q = 0; q < 8; ++q) acc2[q] = 0ull;
    float sA = 0.f;
    const int d4b = w * 4;

    #pragma unroll 8
    for (int p = 0; p < PPB; ++p) {
        float a = As[p * AS_STRIDE + lane];            // conflict-free (stride 33)
        sA += a;
        unsigned long long a2 = pack2(a, a);
        #pragma unroll
        for (int q = 0; q < 4; ++q) {
            ulonglong2 xv = xs2[p * XS_STRIDE + d4b + q];   // uniform -> broadcast
            acc2[2 * q + 0] = ffma2_(a2, xv.x, acc2[2 * q + 0]);
            acc2[2 * q + 1] = ffma2_(a2, xv.y, acc2[2 * q + 1]);
        }
    }

    // ---- epilogue: partial tile -> g_Ep[chunk][d][k], coalesced STG.32 ----
    float* ep = g_Ep + (size_t)blockIdx.x * (KK * DD);
    const float4* crow = (const float4*)(cw + (size_t)lane * DD);
    #pragma unroll
    for (int q = 0; q < 4; ++q) {
        int d4 = d4b + q;
        float4 c = crow[d4];
        float2 lo = unpack2(acc2[2 * q + 0]);
        float2 hi = unpack2(acc2[2 * q + 1]);
        ep[(4 * d4 + 0) * KK + lane] = fmaf(-sA, c.x, lo.x);
        ep[(4 * d4 + 1) * KK + lane] = fmaf(-sA, c.y, lo.y);
        ep[(4 * d4 + 2) * KK + lane] = fmaf(-sA, c.z, hi.x);
        ep[(4 * d4 + 3) * KK + lane] = fmaf(-sA, c.w, hi.y);
    }
}

// out[b][k][d] = sum_{c=0..15} g_Ep[b*16+c][d][k]
__global__ __launch_bounds__(NTHREADS)
void ev_reduce_kernel(float* __restrict__ out) {
    int idx = blockIdx.x * NTHREADS + threadIdx.x;   // 0..65535
    int k = idx & 31;
    int m = idx >> 5;          // 0..2047
    int d = m & 127;
    int b = m >> 7;
    const float* p = g_Ep + ((size_t)b * GPB) * (KK * DD) + d * KK + k;
    float s = 0.f;
    #pragma unroll
    for (int c = 0; c < GPB; ++c) s += p[(size_t)c * (KK * DD)];
    out[((size_t)b * KK + k) * DD + d] = s;
}

extern "C" void kernel_launch(void* const* d_in, const int* in_sizes, int n_in,
                              void* d_out, int out_size) {
    const float* x  = (const float*)d_in[0];   // [16,32,32,128]
    const float* cw = (const float*)d_in[1];   // [32,128]
    const float* sc = (const float*)d_in[2];   // [32]
    float* out = (float*)d_out;                // [16,32,128]

    cudaFuncSetAttribute(ev_encode_kernel,
                         cudaFuncAttributeMaxDynamicSharedMemorySize, SMEM_BYTES);

    ev_encode_kernel<<<NCHUNK, NTHREADS, SMEM_BYTES>>>(x, cw, sc);
    ev_reduce_kernel<<<(BB * KK * DD) / NTHREADS, NTHREADS>>>(out);
}